// round 5
// baseline (speedup 1.0000x reference)
#include <cuda_runtime.h>

#define BATCH 32
#define CH    64
#define NPIX  (192*192)      // 36864
#define SPLITS 16
#define NPER  (NPIX/SPLITS)  // 2304
#define TA    64             // N-chunk for energy kernel
#define TN    256            // N-tile for out kernel

// Scratch (device globals — no allocation allowed)
__device__ float g_energy[BATCH*CH*CH];   // 512 KB
__device__ float g_attn[BATCH*CH*CH];     // 512 KB

__global__ void zero_energy_kernel() {
    int stride = gridDim.x * blockDim.x;
    for (int i = blockIdx.x*blockDim.x + threadIdx.x; i < BATCH*CH*CH; i += stride)
        g_energy[i] = 0.0f;
}

// ---------------------------------------------------------------------------
// energy[b,c,d] = sum_n q[b,c,n]*q[b,d,n]
// grid (SPLITS, BATCH), 256 threads = 16x16 (cg, dg), 4x4 accumulators/thread.
// Smem layout: float4 slots, slot(n,chg) = (n<<4) | (chg ^ (n&15)).
// float4 packs 4 consecutive channels at one n -> both compute loads and the
// transpose-store hit the structural smem phase floor.
// ---------------------------------------------------------------------------
__global__ __launch_bounds__(256) void energy_kernel(const float* __restrict__ x) {
    __shared__ float4 qs4[TA*16];   // 64 n x 16 float4 = 16 KB

    const int b = blockIdx.y;
    const int s = blockIdx.x;
    const float* q = x + (size_t)b * CH * NPIX;
    const int t  = threadIdx.x;
    const int ty = t >> 4;          // cg 0..15
    const int tx = t & 15;          // dg 0..15

    float acc[4][4];
#pragma unroll
    for (int i = 0; i < 4; i++)
#pragma unroll
        for (int j = 0; j < 4; j++) acc[i][j] = 0.0f;

    const int n_base = s * NPER;

    for (int chunk = 0; chunk < NPER; chunk += TA) {
        __syncthreads();
        // Load 64ch x 64n: each thread 4 iterations of 4 strided scalar LDGs
        // (coalesced along n), packed into one float4 smem store.
#pragma unroll
        for (int i = 0; i < 4; i++) {
            int flat = t + i*256;           // 0..1023
            int n    = flat & 63;
            int chg  = flat >> 6;           // 0..15
            const float* p = q + (size_t)(chg*4) * NPIX + n_base + chunk + n;
            float4 v;
            v.x = p[0];
            v.y = p[NPIX];
            v.z = p[2*NPIX];
            v.w = p[3*NPIX];
            qs4[(n << 4) | (chg ^ (n & 15))] = v;
        }
        __syncthreads();

#pragma unroll 8
        for (int n = 0; n < TA; n++) {
            int row = (n << 4);
            int sw  = (n & 15);
            float4 qc = qs4[row | (ty ^ sw)];   // q[c0..c0+3][n]
            float4 qd = qs4[row | (tx ^ sw)];   // q[d0..d0+3][n]
            float c[4] = {qc.x, qc.y, qc.z, qc.w};
            float d[4] = {qd.x, qd.y, qd.z, qd.w};
#pragma unroll
            for (int i = 0; i < 4; i++)
#pragma unroll
                for (int j = 0; j < 4; j++)
                    acc[i][j] = fmaf(c[i], d[j], acc[i][j]);
        }
    }

    float* eb = g_energy + b * CH * CH;
    const int c0 = ty*4, d0 = tx*4;
#pragma unroll
    for (int i = 0; i < 4; i++)
#pragma unroll
        for (int j = 0; j < 4; j++)
            atomicAdd(&eb[(c0+i)*CH + (d0+j)], acc[i][j]);
}

// ---------------------------------------------------------------------------
// attention = softmax(rowmax - energy)  ==  exp(rowmin - e) / sum
// one warp per row (BATCH*CH = 2048 rows)
// ---------------------------------------------------------------------------
__global__ __launch_bounds__(256) void softmax_kernel() {
    int gw   = (blockIdx.x * blockDim.x + threadIdx.x) >> 5;
    int lane = threadIdx.x & 31;
    if (gw >= BATCH*CH) return;
    const float* e = g_energy + gw * CH;
    float* a = g_attn + gw * CH;
    float e0 = e[lane], e1 = e[lane + 32];
    float mn = fminf(e0, e1);
#pragma unroll
    for (int o = 16; o; o >>= 1) mn = fminf(mn, __shfl_xor_sync(0xFFFFFFFFu, mn, o));
    float v0 = expf(mn - e0);
    float v1 = expf(mn - e1);
    float sum = v0 + v1;
#pragma unroll
    for (int o = 16; o; o >>= 1) sum += __shfl_xor_sync(0xFFFFFFFFu, sum, o);
    float inv = 1.0f / sum;
    a[lane]      = v0 * inv;
    a[lane + 32] = v1 * inv;
}

// ---------------------------------------------------------------------------
// out[b,c,n] = sum_d attn[b,c,d] * q[b,d,n];  final = x*(gamma*out) + x
// grid (NPIX/TN, BATCH), 256 threads: ty=t/64 (4 c-groups), tx=t%64 (n-group).
// Outer cg loop x4 covers all 64 output channels reusing smem tiles.
// dyn smem: qs[64][260] (x tile, also reused as x in epilogue) + attn[64][68]
// ---------------------------------------------------------------------------
#define QLD 260
#define ALD 68
#define SMEM_C ((CH*QLD + CH*ALD) * sizeof(float))

__global__ __launch_bounds__(256) void out_kernel(const float* __restrict__ x,
                                                  const float* __restrict__ gamma,
                                                  float* __restrict__ out) {
    extern __shared__ float sm[];
    float* qs = sm;                 // [64][260]
    float* as_ = sm + CH*QLD;       // [64][68]

    const int b  = blockIdx.y;
    const int n0 = blockIdx.x * TN;
    const float* q = x + (size_t)b * CH * NPIX;
    const int t = threadIdx.x;

    // attn tile: 64x64 floats = 1024 float4, 4 per thread
    const float* ab = g_attn + b * CH * CH;
#pragma unroll
    for (int i = 0; i < 4; i++) {
        int flat = t + i*256;
        int ch = flat >> 4;
        int df = (flat & 15) << 2;
        *(float4*)&as_[ch*ALD + df] = *(const float4*)(ab + ch*CH + df);
    }
    // q tile: 64ch x 256n = 4096 float4, 16 per thread
#pragma unroll
    for (int i = 0; i < 16; i++) {
        int flat = t + i*256;       // 0..4095
        int ch = flat >> 6;
        int nf = (flat & 63) << 2;
        *(float4*)&qs[ch*QLD + nf] = *(const float4*)(q + (size_t)ch*NPIX + n0 + nf);
    }
    __syncthreads();

    const float g = gamma[0];
    const int ty = t >> 6;          // 0..3
    const int tx = t & 63;          // 0..63
    const int nn = tx * 4;

    for (int cg = 0; cg < 4; cg++) {
        const int c0 = cg*16 + ty*4;
        float4 acc[4];
#pragma unroll
        for (int i = 0; i < 4; i++) acc[i] = make_float4(0.f, 0.f, 0.f, 0.f);

#pragma unroll
        for (int d = 0; d < CH; d += 4) {
            float4 qv[4];
#pragma unroll
            for (int j = 0; j < 4; j++) qv[j] = *(float4*)&qs[(d+j)*QLD + nn];
#pragma unroll
            for (int i = 0; i < 4; i++) {
                float4 av = *(float4*)&as_[(c0+i)*ALD + d];
                acc[i].x = fmaf(av.x, qv[0].x, acc[i].x);
                acc[i].y = fmaf(av.x, qv[0].y, acc[i].y);
                acc[i].z = fmaf(av.x, qv[0].z, acc[i].z);
                acc[i].w = fmaf(av.x, qv[0].w, acc[i].w);
                acc[i].x = fmaf(av.y, qv[1].x, acc[i].x);
                acc[i].y = fmaf(av.y, qv[1].y, acc[i].y);
                acc[i].z = fmaf(av.y, qv[1].z, acc[i].z);
                acc[i].w = fmaf(av.y, qv[1].w, acc[i].w);
                acc[i].x = fmaf(av.z, qv[2].x, acc[i].x);
                acc[i].y = fmaf(av.z, qv[2].y, acc[i].y);
                acc[i].z = fmaf(av.z, qv[2].z, acc[i].z);
                acc[i].w = fmaf(av.z, qv[2].w, acc[i].w);
                acc[i].x = fmaf(av.w, qv[3].x, acc[i].x);
                acc[i].y = fmaf(av.w, qv[3].y, acc[i].y);
                acc[i].z = fmaf(av.w, qv[3].z, acc[i].z);
                acc[i].w = fmaf(av.w, qv[3].w, acc[i].w);
            }
        }

        // epilogue: x value is the q tile itself
#pragma unroll
        for (int i = 0; i < 4; i++) {
            int c = c0 + i;
            float4 xv = *(float4*)&qs[c*QLD + nn];
            float4 r;
            r.x = fmaf(xv.x, g * acc[i].x, xv.x);
            r.y = fmaf(xv.y, g * acc[i].y, xv.y);
            r.z = fmaf(xv.z, g * acc[i].z, xv.z);
            r.w = fmaf(xv.w, g * acc[i].w, xv.w);
            *(float4*)(out + (size_t)(b*CH + c)*NPIX + n0 + nn) = r;
        }
    }
}

extern "C" void kernel_launch(void* const* d_in, const int* in_sizes, int n_in,
                              void* d_out, int out_size) {
    const float* x     = (const float*)d_in[0];
    const float* gamma = (const float*)d_in[1];
    float* out         = (float*)d_out;

    zero_energy_kernel<<<128, 256>>>();
    energy_kernel<<<dim3(SPLITS, BATCH), 256>>>(x);
    softmax_kernel<<<(BATCH*CH*32 + 255) / 256, 256>>>();
    cudaFuncSetAttribute(out_kernel, cudaFuncAttributeMaxDynamicSharedMemorySize, (int)SMEM_C);
    out_kernel<<<dim3(NPIX/TN, BATCH), 256, SMEM_C>>>(x, gamma, out);
}

// round 7
// speedup vs baseline: 3.3733x; 3.3733x over previous
#include <cuda_runtime.h>
#include <cuda_bf16.h>
#include <cstdint>

#define BATCH 32
#define CH    64
#define NPIX  (192*192)      // 36864
#define SPLITS 16
#define NPER  (NPIX/SPLITS)  // 2304
#define KC    128            // K-chunk per stage (energy)
#define STAGES (NPER/KC)     // 18
#define TN    128            // N-tile for out kernel

// Scratch (device globals — no allocation allowed)
__device__ __align__(16) float g_energy[BATCH*CH*CH];   // 512 KB
__device__ __align__(16) float g_attn[BATCH*CH*CH];     // 512 KB

__device__ __forceinline__ unsigned smem_u32(const void* p) {
    return (unsigned)__cvta_generic_to_shared(p);
}

__device__ __forceinline__ unsigned pack2bf(float a, float b) {
    __nv_bfloat162 h = __floats2bfloat162_rn(a, b);
    return *reinterpret_cast<unsigned*>(&h);
}

#define LDSM4(r0,r1,r2,r3,addr) \
    asm volatile("ldmatrix.sync.aligned.m8n8.x4.shared.b16 {%0,%1,%2,%3}, [%4];" \
        : "=r"(r0),"=r"(r1),"=r"(r2),"=r"(r3) : "r"(addr))

#define LDSM4T(r0,r1,r2,r3,addr) \
    asm volatile("ldmatrix.sync.aligned.m8n8.x4.trans.shared.b16 {%0,%1,%2,%3}, [%4];" \
        : "=r"(r0),"=r"(r1),"=r"(r2),"=r"(r3) : "r"(addr))

#define MMA16816(C,a0,a1,a2,a3,b0,b1) \
    asm volatile("mma.sync.aligned.m16n8k16.row.col.f32.bf16.bf16.f32 " \
        "{%0,%1,%2,%3}, {%4,%5,%6,%7}, {%8,%9}, {%0,%1,%2,%3};" \
        : "+f"((C)[0]),"+f"((C)[1]),"+f"((C)[2]),"+f"((C)[3]) \
        : "r"(a0),"r"(a1),"r"(a2),"r"(a3),"r"(b0),"r"(b1))

__global__ void zero_energy_kernel() {
    int stride = gridDim.x * blockDim.x;
    for (int i = blockIdx.x*blockDim.x + threadIdx.x; i < BATCH*CH*CH; i += stride)
        g_energy[i] = 0.0f;
}

// ---------------------------------------------------------------------------
// energy[b,c,d] = sum_n q[b,c,n]*q[b,d,n]  — bf16 tensor-core, fp32 accum.
// grid (SPLITS, BATCH), 256 threads (8 warps).
// Smem tile: bf16 [64 ch][128 k] as 16B chunks, chunk index = c*16 + (j ^ (c&7)).
// Warp w: c-tile = (w&3)*16, d-tile = (w>>2)*32 (4 n-subtiles of 8).
// Double smem buffer, register-staged global loads, 1 sync/stage.
// ---------------------------------------------------------------------------
__global__ __launch_bounds__(256) void energy_kernel(const float* __restrict__ x) {
    __shared__ uint4 sm[2][CH*16];   // 2 x 16 KB

    const int b = blockIdx.y;
    const int split = blockIdx.x;
    const float* q = x + (size_t)b * CH * NPIX;
    const int t = threadIdx.x;
    const int kb0 = split * NPER;

    uint4 stg[4];

    // prefetch stage 0
#pragma unroll
    for (int i = 0; i < 4; i++) {
        int id = t + i*256;            // 0..1023
        int c = id >> 4, j = id & 15;  // c row, 16B chunk (8 k) along k
        const float4* p = (const float4*)(q + (size_t)c*NPIX + kb0 + j*8);
        float4 v0 = p[0], v1 = p[1];
        stg[i] = make_uint4(pack2bf(v0.x,v0.y), pack2bf(v0.z,v0.w),
                            pack2bf(v1.x,v1.y), pack2bf(v1.z,v1.w));
    }

    const int L = t & 31, w = t >> 5;
    const int cw = (w & 3) << 4;
    const int dw = (w >> 2) << 5;
    const int r = L & 7, m = L >> 3;

    float acc[4][4];
#pragma unroll
    for (int i = 0; i < 4; i++)
#pragma unroll
        for (int jj = 0; jj < 4; jj++) acc[i][jj] = 0.0f;

    const int ca = cw + r + (m & 1)*8;      // A-frag row
    const int ja = (m >> 1);                // A-frag chunk offset
    const int dbase = dw + (m >> 1)*8 + r;  // B-frag row (per pair add p*16)
    const int jb = (m & 1);                 // B-frag chunk offset

    for (int s = 0; s < STAGES; s++) {
        uint4* buf = sm[s & 1];
#pragma unroll
        for (int i = 0; i < 4; i++) {
            int id = t + i*256;
            int c = id >> 4, j = id & 15;
            buf[c*16 + (j ^ (c & 7))] = stg[i];
        }
        __syncthreads();

        if (s + 1 < STAGES) {
            int kb = kb0 + (s + 1)*KC;
#pragma unroll
            for (int i = 0; i < 4; i++) {
                int id = t + i*256;
                int c = id >> 4, j = id & 15;
                const float4* p = (const float4*)(q + (size_t)c*NPIX + kb + j*8);
                float4 v0 = p[0], v1 = p[1];
                stg[i] = make_uint4(pack2bf(v0.x,v0.y), pack2bf(v0.z,v0.w),
                                    pack2bf(v1.x,v1.y), pack2bf(v1.z,v1.w));
            }
        }

        unsigned base = smem_u32(buf);
#pragma unroll
        for (int kk8 = 0; kk8 < 16; kk8 += 2) {   // 8 k-steps of 16
            unsigned a0,a1,a2,a3;
            unsigned aaddr = base + (unsigned)(ca*16 + ((kk8 + ja) ^ (ca & 7)))*16u;
            LDSM4(a0,a1,a2,a3,aaddr);
#pragma unroll
            for (int p = 0; p < 2; p++) {
                int db = dbase + p*16;
                unsigned b0,b1,b2,b3;
                unsigned baddr = base + (unsigned)(db*16 + ((kk8 + jb) ^ (db & 7)))*16u;
                LDSM4(b0,b1,b2,b3,baddr);
                MMA16816(acc[p*2+0], a0,a1,a2,a3, b0,b1);
                MMA16816(acc[p*2+1], a0,a1,a2,a3, b2,b3);
            }
        }
    }

    // epilogue: atomic accumulate into g_energy
    float* eb = g_energy + b*CH*CH;
    const int row  = cw + (L >> 2);
    const int colb = dw + (L & 3)*2;
#pragma unroll
    for (int nt = 0; nt < 4; nt++) {
        int col = colb + nt*8;
        atomicAdd(&eb[row*CH + col],       acc[nt][0]);
        atomicAdd(&eb[row*CH + col + 1],   acc[nt][1]);
        atomicAdd(&eb[(row+8)*CH + col],   acc[nt][2]);
        atomicAdd(&eb[(row+8)*CH + col+1], acc[nt][3]);
    }
}

// ---------------------------------------------------------------------------
// attention = softmax(rowmax - energy)  ==  exp(rowmin - e) / sum
// ---------------------------------------------------------------------------
__global__ __launch_bounds__(256) void softmax_kernel() {
    int gw   = (blockIdx.x * blockDim.x + threadIdx.x) >> 5;
    int lane = threadIdx.x & 31;
    if (gw >= BATCH*CH) return;
    const float* e = g_energy + gw * CH;
    float* a = g_attn + gw * CH;
    float e0 = e[lane], e1 = e[lane + 32];
    float mn = fminf(e0, e1);
#pragma unroll
    for (int o = 16; o; o >>= 1) mn = fminf(mn, __shfl_xor_sync(0xFFFFFFFFu, mn, o));
    float v0 = expf(mn - e0);
    float v1 = expf(mn - e1);
    float sum = v0 + v1;
#pragma unroll
    for (int o = 16; o; o >>= 1) sum += __shfl_xor_sync(0xFFFFFFFFu, sum, o);
    float inv = 1.0f / sum;
    a[lane]      = v0 * inv;
    a[lane + 32] = v1 * inv;
}

// ---------------------------------------------------------------------------
// out[b,c,n] = sum_d attn[b,c,d]*q[b,d,n]; res = fmaf(x, g*out, x) (fp32 x).
// grid (NPIX/TN, BATCH), 256 threads. A = attn (row-major c x d, bf16 smem),
// B = q tile [d][TN n] bf16 smem, fragments via ldmatrix.trans.
// Warp w: c-tile = (w&3)*16, n-range = (w>>2)*64 (8 subtiles of 8).
// ---------------------------------------------------------------------------
__global__ __launch_bounds__(256) void out_kernel(const float* __restrict__ x,
                                                  const float* __restrict__ gamma,
                                                  float* __restrict__ out) {
    __shared__ uint4 sa[CH*8];    // attn bf16 64x64  (8 KB)
    __shared__ uint4 sq[CH*16];   // q    bf16 64x128 (16 KB)

    const int b  = blockIdx.y;
    const int n0 = blockIdx.x * TN;
    const int t  = threadIdx.x;
    const float* q = x + (size_t)b * CH * NPIX;

    // attn tile: 512 chunks of 8 floats -> bf16
    const float* ab = g_attn + b*CH*CH;
#pragma unroll
    for (int i = 0; i < 2; i++) {
        int id = t + i*256;           // 0..511
        int c = id >> 3, j = id & 7;
        const float4* p = (const float4*)(ab + c*CH + j*8);
        float4 v0 = p[0], v1 = p[1];
        sa[c*8 + (j ^ (c & 7))] = make_uint4(pack2bf(v0.x,v0.y), pack2bf(v0.z,v0.w),
                                             pack2bf(v1.x,v1.y), pack2bf(v1.z,v1.w));
    }
    // q tile: 1024 chunks
#pragma unroll
    for (int i = 0; i < 4; i++) {
        int id = t + i*256;           // 0..1023
        int d = id >> 4, j = id & 15;
        const float4* p = (const float4*)(q + (size_t)d*NPIX + n0 + j*8);
        float4 v0 = p[0], v1 = p[1];
        sq[d*16 + (j ^ (d & 7))] = make_uint4(pack2bf(v0.x,v0.y), pack2bf(v0.z,v0.w),
                                              pack2bf(v1.x,v1.y), pack2bf(v1.z,v1.w));
    }
    __syncthreads();

    const int L = t & 31, w = t >> 5;
    const int cw = (w & 3) << 4;
    const int nb = (w >> 2) << 6;     // 0 or 64
    const int r = L & 7, m = L >> 3;

    // preload A fragments (k = 0..63, 4 k-steps)
    unsigned A[4][4];
    {
        unsigned abase = smem_u32(sa);
        int ca = cw + r + (m & 1)*8;
#pragma unroll
        for (int ks = 0; ks < 4; ks++) {
            unsigned addr = abase + (unsigned)(ca*8 + ((ks*2 + (m >> 1)) ^ (ca & 7)))*16u;
            LDSM4(A[ks][0], A[ks][1], A[ks][2], A[ks][3], addr);
        }
    }

    float acc[8][4];
#pragma unroll
    for (int i = 0; i < 8; i++)
#pragma unroll
        for (int jj = 0; jj < 4; jj++) acc[i][jj] = 0.0f;

    unsigned qbase = smem_u32(sq);
#pragma unroll
    for (int ks = 0; ks < 4; ks++) {
        int d = ks*16 + (m & 1)*8 + r;          // k-row for this lane
        int jrow = d*16;
        int jsw  = d & 7;
#pragma unroll
        for (int p = 0; p < 4; p++) {           // pairs of n-subtiles
            int jn = (nb >> 3) + p*2 + (m >> 1);
            unsigned b0,b1,b2,b3;
            unsigned addr = qbase + (unsigned)(jrow + (jn ^ jsw))*16u;
            LDSM4T(b0,b1,b2,b3,addr);
            MMA16816(acc[p*2+0], A[ks][0],A[ks][1],A[ks][2],A[ks][3], b0,b1);
            MMA16816(acc[p*2+1], A[ks][0],A[ks][1],A[ks][2],A[ks][3], b2,b3);
        }
    }

    // epilogue: fp32 x (L1-hot), res = fmaf(x, g*acc, x)
    const float g = gamma[0];
    const int row = cw + (L >> 2);
    const int colp = (L & 3)*2;
    const size_t base0 = (size_t)(b*CH + row)*NPIX + n0 + nb + colp;
    const float* xr0 = x + base0;
    const float* xr1 = xr0 + (size_t)8*NPIX;
    float* o0 = out + base0;
    float* o1 = o0 + (size_t)8*NPIX;
#pragma unroll
    for (int nt = 0; nt < 8; nt++) {
        int off = nt*8;
        float2 xv0 = *(const float2*)(xr0 + off);
        float2 xv1 = *(const float2*)(xr1 + off);
        float2 r0, r1;
        r0.x = fmaf(xv0.x, g*acc[nt][0], xv0.x);
        r0.y = fmaf(xv0.y, g*acc[nt][1], xv0.y);
        r1.x = fmaf(xv1.x, g*acc[nt][2], xv1.x);
        r1.y = fmaf(xv1.y, g*acc[nt][3], xv1.y);
        *(float2*)(o0 + off) = r0;
        *(float2*)(o1 + off) = r1;
    }
}

extern "C" void kernel_launch(void* const* d_in, const int* in_sizes, int n_in,
                              void* d_out, int out_size) {
    const float* x     = (const float*)d_in[0];
    const float* gamma = (const float*)d_in[1];
    float* out         = (float*)d_out;

    zero_energy_kernel<<<128, 256>>>();
    energy_kernel<<<dim3(SPLITS, BATCH), 256>>>(x);
    softmax_kernel<<<(BATCH*CH*32 + 255) / 256, 256>>>();
    out_kernel<<<dim3(NPIX/TN, BATCH), 256>>>(x, gamma, out);
}

// round 9
// speedup vs baseline: 3.9727x; 1.1777x over previous
#include <cuda_runtime.h>
#include <cuda_bf16.h>
#include <cstdint>

#define BATCH 32
#define CH    64
#define NPIX  (192*192)      // 36864
#define SPLITS 32
#define NPER  (NPIX/SPLITS)  // 1152
#define KC    128            // K-chunk per stage (energy)
#define STAGES (NPER/KC)     // 9
#define TN    128            // N-tile for out kernel

// out_kernel dynamic smem layout (floats/uint4s):
#define XLD   132                          // xs row stride (floats)
#define XS_FLOATS (CH*XLD)                 // 8448 floats = 33792 B
#define SA_U4 (CH*8)                       // 8 KB
#define SQ_U4 (CH*16)                      // 16 KB
#define SMEM_OUT (XS_FLOATS*4 + SA_U4*16 + SQ_U4*16)   // 58368 B
#define STG_STRIDE 72                      // staging row stride (floats)
#define STG_PER_WARP (8*STG_STRIDE)        // 576 floats

// Scratch (device globals — no allocation allowed)
__device__ __align__(16) float g_energy[BATCH*CH*CH];   // 512 KB
__device__ __align__(16) float g_attn[BATCH*CH*CH];     // 512 KB

__device__ __forceinline__ unsigned smem_u32(const void* p) {
    return (unsigned)__cvta_generic_to_shared(p);
}

__device__ __forceinline__ unsigned pack2bf(float a, float b) {
    __nv_bfloat162 h = __floats2bfloat162_rn(a, b);
    return *reinterpret_cast<unsigned*>(&h);
}

#define LDSM4(r0,r1,r2,r3,addr) \
    asm volatile("ldmatrix.sync.aligned.m8n8.x4.shared.b16 {%0,%1,%2,%3}, [%4];" \
        : "=r"(r0),"=r"(r1),"=r"(r2),"=r"(r3) : "r"(addr))

#define LDSM4T(r0,r1,r2,r3,addr) \
    asm volatile("ldmatrix.sync.aligned.m8n8.x4.trans.shared.b16 {%0,%1,%2,%3}, [%4];" \
        : "=r"(r0),"=r"(r1),"=r"(r2),"=r"(r3) : "r"(addr))

#define MMA16816(C,a0,a1,a2,a3,b0,b1) \
    asm volatile("mma.sync.aligned.m16n8k16.row.col.f32.bf16.bf16.f32 " \
        "{%0,%1,%2,%3}, {%4,%5,%6,%7}, {%8,%9}, {%0,%1,%2,%3};" \
        : "+f"((C)[0]),"+f"((C)[1]),"+f"((C)[2]),"+f"((C)[3]) \
        : "r"(a0),"r"(a1),"r"(a2),"r"(a3),"r"(b0),"r"(b1))

__global__ void zero_energy_kernel() {
    int stride = gridDim.x * blockDim.x;
    for (int i = blockIdx.x*blockDim.x + threadIdx.x; i < BATCH*CH*CH; i += stride)
        g_energy[i] = 0.0f;
}

// ---------------------------------------------------------------------------
// energy[b,c,d] = sum_n q[b,c,n]*q[b,d,n]  — bf16 tensor-core, fp32 accum.
// grid (SPLITS, BATCH), 256 threads (8 warps).
// ---------------------------------------------------------------------------
__global__ __launch_bounds__(256) void energy_kernel(const float* __restrict__ x) {
    __shared__ uint4 sm[2][CH*16];   // 2 x 16 KB

    const int b = blockIdx.y;
    const int split = blockIdx.x;
    const float* q = x + (size_t)b * CH * NPIX;
    const int t = threadIdx.x;
    const int kb0 = split * NPER;

    uint4 stg[4];

    // prefetch stage 0
#pragma unroll
    for (int i = 0; i < 4; i++) {
        int id = t + i*256;            // 0..1023
        int c = id >> 4, j = id & 15;  // c row, 16B chunk (8 k) along k
        const float4* p = (const float4*)(q + (size_t)c*NPIX + kb0 + j*8);
        float4 v0 = p[0], v1 = p[1];
        stg[i] = make_uint4(pack2bf(v0.x,v0.y), pack2bf(v0.z,v0.w),
                            pack2bf(v1.x,v1.y), pack2bf(v1.z,v1.w));
    }

    const int L = t & 31, w = t >> 5;
    const int cw = (w & 3) << 4;
    const int dw = (w >> 2) << 5;
    const int r = L & 7, m = L >> 3;

    float acc[4][4];
#pragma unroll
    for (int i = 0; i < 4; i++)
#pragma unroll
        for (int jj = 0; jj < 4; jj++) acc[i][jj] = 0.0f;

    const int ca = cw + r + (m & 1)*8;      // A-frag row
    const int ja = (m >> 1);                // A-frag chunk offset
    const int dbase = dw + (m >> 1)*8 + r;  // B-frag row (per pair add p*16)
    const int jb = (m & 1);                 // B-frag chunk offset

    for (int s = 0; s < STAGES; s++) {
        uint4* buf = sm[s & 1];
#pragma unroll
        for (int i = 0; i < 4; i++) {
            int id = t + i*256;
            int c = id >> 4, j = id & 15;
            buf[c*16 + (j ^ (c & 7))] = stg[i];
        }
        __syncthreads();

        if (s + 1 < STAGES) {
            int kb = kb0 + (s + 1)*KC;
#pragma unroll
            for (int i = 0; i < 4; i++) {
                int id = t + i*256;
                int c = id >> 4, j = id & 15;
                const float4* p = (const float4*)(q + (size_t)c*NPIX + kb + j*8);
                float4 v0 = p[0], v1 = p[1];
                stg[i] = make_uint4(pack2bf(v0.x,v0.y), pack2bf(v0.z,v0.w),
                                    pack2bf(v1.x,v1.y), pack2bf(v1.z,v1.w));
            }
        }

        unsigned base = smem_u32(buf);
#pragma unroll
        for (int kk8 = 0; kk8 < 16; kk8 += 2) {   // 8 k-steps of 16
            unsigned a0,a1,a2,a3;
            unsigned aaddr = base + (unsigned)(ca*16 + ((kk8 + ja) ^ (ca & 7)))*16u;
            LDSM4(a0,a1,a2,a3,aaddr);
#pragma unroll
            for (int p = 0; p < 2; p++) {
                int db = dbase + p*16;
                unsigned b0,b1,b2,b3;
                unsigned baddr = base + (unsigned)(db*16 + ((kk8 + jb) ^ (db & 7)))*16u;
                LDSM4(b0,b1,b2,b3,baddr);
                MMA16816(acc[p*2+0], a0,a1,a2,a3, b0,b1);
                MMA16816(acc[p*2+1], a0,a1,a2,a3, b2,b3);
            }
        }
        __syncthreads();
    }

    // epilogue: atomic accumulate into g_energy
    float* eb = g_energy + b*CH*CH;
    const int row  = cw + (L >> 2);
    const int colb = dw + (L & 3)*2;
#pragma unroll
    for (int nt = 0; nt < 4; nt++) {
        int col = colb + nt*8;
        atomicAdd(&eb[row*CH + col],       acc[nt][0]);
        atomicAdd(&eb[row*CH + col + 1],   acc[nt][1]);
        atomicAdd(&eb[(row+8)*CH + col],   acc[nt][2]);
        atomicAdd(&eb[(row+8)*CH + col+1], acc[nt][3]);
    }
}

// ---------------------------------------------------------------------------
// attention = softmax(rowmax - energy)  ==  exp(rowmin - e) / sum
// ---------------------------------------------------------------------------
__global__ __launch_bounds__(256) void softmax_kernel() {
    int gw   = (blockIdx.x * blockDim.x + threadIdx.x) >> 5;
    int lane = threadIdx.x & 31;
    if (gw >= BATCH*CH) return;
    const float* e = g_energy + gw * CH;
    float* a = g_attn + gw * CH;
    float e0 = e[lane], e1 = e[lane + 32];
    float mn = fminf(e0, e1);
#pragma unroll
    for (int o = 16; o; o >>= 1) mn = fminf(mn, __shfl_xor_sync(0xFFFFFFFFu, mn, o));
    float v0 = expf(mn - e0);
    float v1 = expf(mn - e1);
    float sum = v0 + v1;
#pragma unroll
    for (int o = 16; o; o >>= 1) sum += __shfl_xor_sync(0xFFFFFFFFu, sum, o);
    float inv = 1.0f / sum;
    a[lane]      = v0 * inv;
    a[lane + 32] = v1 * inv;
}

// ---------------------------------------------------------------------------
// out[b,c,n] = sum_d attn[b,c,d]*q[b,d,n]; res = fmaf(x, g*out, x).
// x tile is read from global ONCE: fp32 copy kept in smem (xs) for the
// epilogue, bf16 copy (sq) for ldmatrix. Accumulators staged through
// warp-private smem (overlaying sa/sq after compute) for coalesced stores.
// ---------------------------------------------------------------------------
__global__ __launch_bounds__(256) void out_kernel(const float* __restrict__ x,
                                                  const float* __restrict__ gamma,
                                                  float* __restrict__ out) {
    extern __shared__ float smdyn[];
    float* xs = smdyn;                                   // [64][132] fp32
    uint4* sa = (uint4*)(smdyn + XS_FLOATS);             // attn bf16 64x64
    uint4* sq = sa + SA_U4;                              // q bf16 64x128
    float* stage = (float*)sa;                           // overlay after compute

    const int b  = blockIdx.y;
    const int n0 = blockIdx.x * TN;
    const int t  = threadIdx.x;
    const float* q = x + (size_t)b * CH * NPIX;

    // attn tile: 512 chunks of 8 floats -> bf16
    const float* ab = g_attn + b*CH*CH;
#pragma unroll
    for (int i = 0; i < 2; i++) {
        int id = t + i*256;           // 0..511
        int c = id >> 3, j = id & 7;
        const float4* p = (const float4*)(ab + c*CH + j*8);
        float4 v0 = p[0], v1 = p[1];
        sa[c*8 + (j ^ (c & 7))] = make_uint4(pack2bf(v0.x,v0.y), pack2bf(v0.z,v0.w),
                                             pack2bf(v1.x,v1.y), pack2bf(v1.z,v1.w));
    }
    // x tile: single global read -> fp32 xs + bf16 sq
#pragma unroll
    for (int i = 0; i < 4; i++) {
        int id = t + i*256;           // 0..1023
        int d = id >> 4, j = id & 15;
        const float4* p = (const float4*)(q + (size_t)d*NPIX + n0 + j*8);
        float4 v0 = p[0], v1 = p[1];
        sq[d*16 + (j ^ (d & 7))] = make_uint4(pack2bf(v0.x,v0.y), pack2bf(v0.z,v0.w),
                                              pack2bf(v1.x,v1.y), pack2bf(v1.z,v1.w));
        float* xr = xs + d*XLD + j*8;
        *(float4*)xr       = v0;
        *(float4*)(xr + 4) = v1;
    }
    __syncthreads();

    const int L = t & 31, w = t >> 5;
    const int cw = (w & 3) << 4;
    const int nb = (w >> 2) << 6;     // 0 or 64
    const int r = L & 7, m = L >> 3;

    // preload A fragments (k = 0..63, 4 k-steps)
    unsigned A[4][4];
    {
        unsigned abase = smem_u32(sa);
        int ca = cw + r + (m & 1)*8;
#pragma unroll
        for (int ks = 0; ks < 4; ks++) {
            unsigned addr = abase + (unsigned)(ca*8 + ((ks*2 + (m >> 1)) ^ (ca & 7)))*16u;
            LDSM4(A[ks][0], A[ks][1], A[ks][2], A[ks][3], addr);
        }
    }

    float acc[8][4];
#pragma unroll
    for (int i = 0; i < 8; i++)
#pragma unroll
        for (int jj = 0; jj < 4; jj++) acc[i][jj] = 0.0f;

    unsigned qbase = smem_u32(sq);
#pragma unroll
    for (int ks = 0; ks < 4; ks++) {
        int d = ks*16 + (m & 1)*8 + r;          // k-row for this lane
        int jrow = d*16;
        int jsw  = d & 7;
#pragma unroll
        for (int p = 0; p < 4; p++) {           // pairs of n-subtiles
            int jn = (nb >> 3) + p*2 + (m >> 1);
            unsigned b0,b1,b2,b3;
            unsigned addr = qbase + (unsigned)(jrow + (jn ^ jsw))*16u;
            LDSM4T(b0,b1,b2,b3,addr);
            MMA16816(acc[p*2+0], A[ks][0],A[ks][1],A[ks][2],A[ks][3], b0,b1);
            MMA16816(acc[p*2+1], A[ks][0],A[ks][1],A[ks][2],A[ks][3], b2,b3);
        }
    }

    __syncthreads();   // all warps done reading sa/sq -> safe to overlay stage

    // epilogue: stage acc through warp-private smem, read back coalesced,
    // fuse res = fmaf(x, g*acc, x) with x from xs, store STG.128 runs.
    const float g = gamma[0];
    float* wstage = stage + w * STG_PER_WARP;
    const int srow = L >> 2;          // 0..7
    const int scol = (L & 3) * 2;     // 0,2,4,6
    const int rr = L >> 4;            // 0..1
    const int cn = (L & 15) * 4;      // 0..60

#pragma unroll
    for (int h = 0; h < 2; h++) {     // half 0: rows cw..cw+7, half 1: +8
        // scatter acc into staging (fragment layout)
#pragma unroll
        for (int nt = 0; nt < 8; nt++) {
            float2 v = make_float2(acc[nt][2*h], acc[nt][2*h + 1]);
            *(float2*)&wstage[srow*STG_STRIDE + scol + nt*8] = v;
        }
        __syncwarp();
        // gather coalesced + epilogue + store
#pragma unroll
        for (int i = 0; i < 4; i++) {
            int row_in = rr + i*2;                 // 0..7
            int crow = cw + h*8 + row_in;
            float4 a4 = *(float4*)&wstage[row_in*STG_STRIDE + cn];
            float4 xv = *(float4*)&xs[crow*XLD + nb + cn];
            float4 res;
            res.x = fmaf(xv.x, g*a4.x, xv.x);
            res.y = fmaf(xv.y, g*a4.y, xv.y);
            res.z = fmaf(xv.z, g*a4.z, xv.z);
            res.w = fmaf(xv.w, g*a4.w, xv.w);
            *(float4*)(out + (size_t)(b*CH + crow)*NPIX + n0 + nb + cn) = res;
        }
        __syncwarp();
    }
}

extern "C" void kernel_launch(void* const* d_in, const int* in_sizes, int n_in,
                              void* d_out, int out_size) {
    const float* x     = (const float*)d_in[0];
    const float* gamma = (const float*)d_in[1];
    float* out         = (float*)d_out;

    zero_energy_kernel<<<128, 256>>>();
    energy_kernel<<<dim3(SPLITS, BATCH), 256>>>(x);
    softmax_kernel<<<(BATCH*CH*32 + 255) / 256, 256>>>();
    cudaFuncSetAttribute(out_kernel, cudaFuncAttributeMaxDynamicSharedMemorySize, SMEM_OUT);
    out_kernel<<<dim3(NPIX/TN, BATCH), 256, SMEM_OUT>>>(x, gamma, out);
}